// round 1
// baseline (speedup 1.0000x reference)
#include <cuda_runtime.h>
#include <math.h>

#define NN 307
#define UU 100
#define FI 103          // UU + 3
#define MAXB 256
#define MAXE 8192

// ---------------- scratch (device globals; no runtime allocation) ----------
__device__ float g_xl[(size_t)MAXB * NN * UU];
__device__ float g_xr[(size_t)MAXB * NN * UU];
__device__ float g_st[(size_t)MAXB * NN * UU];
__device__ int   g_rowptr[NN + 1];
__device__ int   g_col[MAXE + NN + 32];

// ---------------- CSR build over dst (deterministic) ------------------------
__global__ void k_csr_count(const int* __restrict__ dst, int E) {
    __shared__ int c[NN];
    for (int i = threadIdx.x; i < NN; i += blockDim.x) c[i] = 1;  // self loop
    __syncthreads();
    for (int e = threadIdx.x; e < E; e += blockDim.x) atomicAdd(&c[dst[e]], 1);
    __syncthreads();
    if (threadIdx.x == 0) {
        int run = 0;
        for (int i = 0; i < NN; ++i) { g_rowptr[i] = run; run += c[i]; }
        g_rowptr[NN] = run;
    }
}

// one warp (block of 32) per destination node; edge-index order preserved
__global__ void k_csr_fill(const int* __restrict__ src, const int* __restrict__ dst, int E) {
    int d = blockIdx.x;
    int lane = threadIdx.x;
    int pos = g_rowptr[d];
    for (int base = 0; base < E; base += 32) {
        int e = base + lane;
        bool hit = (e < E) && (dst[e] == d);
        unsigned m = __ballot_sync(0xffffffffu, hit);
        if (hit) g_col[pos + __popc(m & ((1u << lane) - 1u))] = src[e];
        pos += __popc(m);
    }
    if (lane == 0) g_col[pos] = d;   // self loop appended last
}

// ---------------- K1: xl = x@Wl, xr = x@Wr  (x = [state | inputs]) ----------
// smem: Wl,Wr (2*103*100 floats) + per-warp 4x104 x-rows
// lane t<25 owns output cols [4t,4t+4); each warp processes 4 rows at a time.
__global__ void __launch_bounds__(256) k_xfrm(
    const float* __restrict__ state, const float* __restrict__ inputs,
    const float* __restrict__ Wl, const float* __restrict__ Wr, int BROWS)
{
    extern __shared__ float sm[];
    float* sW  = sm;                  // [0 .. 20600): Wl then Wr
    float* SXb = sm + 2 * FI * UU;
    for (int i = threadIdx.x; i < FI * UU; i += blockDim.x) {
        sW[i] = Wl[i];
        sW[FI * UU + i] = Wr[i];
    }
    __syncthreads();
    int warp = threadIdx.x >> 5, lane = threadIdx.x & 31, nw = blockDim.x >> 5;
    float* SX = SXb + warp * (4 * 104);
    int ngroups = (BROWS + 3) >> 2;
    for (int g = blockIdx.x * nw + warp; g < ngroups; g += gridDim.x * nw) {
        int row0 = g * 4;
        for (int r = 0; r < 4; ++r) {
            int row = min(row0 + r, BROWS - 1);
            const float* sp = state + (size_t)row * UU;
            for (int i = lane; i < UU; i += 32) SX[r * 104 + i] = sp[i];
            if (lane < 3) {
                int b = row / NN, n = row % NN;
                SX[r * 104 + UU + lane] = inputs[(size_t)b * (NN * 3) + n * 3 + lane];
            }
        }
        __syncwarp();
        if (lane < 25) {
            float accl[4][4] = {}, accr[4][4] = {};
            #pragma unroll 1
            for (int q = 0; q < 25; ++q) {
                float xs[4][4];
                #pragma unroll
                for (int r = 0; r < 4; ++r) {
                    float4 t = *(const float4*)&SX[r * 104 + 4 * q];
                    xs[r][0] = t.x; xs[r][1] = t.y; xs[r][2] = t.z; xs[r][3] = t.w;
                }
                #pragma unroll
                for (int ff = 0; ff < 4; ++ff) {
                    int f = 4 * q + ff;
                    float4 wl = *(const float4*)&sW[f * UU + 4 * lane];
                    float4 wr = *(const float4*)&sW[FI * UU + f * UU + 4 * lane];
                    #pragma unroll
                    for (int r = 0; r < 4; ++r) {
                        float x = xs[r][ff];
                        accl[r][0] = fmaf(x, wl.x, accl[r][0]);
                        accl[r][1] = fmaf(x, wl.y, accl[r][1]);
                        accl[r][2] = fmaf(x, wl.z, accl[r][2]);
                        accl[r][3] = fmaf(x, wl.w, accl[r][3]);
                        accr[r][0] = fmaf(x, wr.x, accr[r][0]);
                        accr[r][1] = fmaf(x, wr.y, accr[r][1]);
                        accr[r][2] = fmaf(x, wr.z, accr[r][2]);
                        accr[r][3] = fmaf(x, wr.w, accr[r][3]);
                    }
                }
            }
            #pragma unroll
            for (int f = 100; f < 103; ++f) {
                float4 wl = *(const float4*)&sW[f * UU + 4 * lane];
                float4 wr = *(const float4*)&sW[FI * UU + f * UU + 4 * lane];
                #pragma unroll
                for (int r = 0; r < 4; ++r) {
                    float x = SX[r * 104 + f];
                    accl[r][0] = fmaf(x, wl.x, accl[r][0]);
                    accl[r][1] = fmaf(x, wl.y, accl[r][1]);
                    accl[r][2] = fmaf(x, wl.z, accl[r][2]);
                    accl[r][3] = fmaf(x, wl.w, accl[r][3]);
                    accr[r][0] = fmaf(x, wr.x, accr[r][0]);
                    accr[r][1] = fmaf(x, wr.y, accr[r][1]);
                    accr[r][2] = fmaf(x, wr.z, accr[r][2]);
                    accr[r][3] = fmaf(x, wr.w, accr[r][3]);
                }
            }
            #pragma unroll
            for (int r = 0; r < 4; ++r) {
                size_t row = min(row0 + r, BROWS - 1);
                *(float4*)&g_xl[row * UU + 4 * lane] =
                    make_float4(accl[r][0], accl[r][1], accl[r][2], accl[r][3]);
                *(float4*)&g_xr[row * UU + 4 * lane] =
                    make_float4(accr[r][0], accr[r][1], accr[r][2], accr[r][3]);
            }
        }
        __syncwarp();
    }
}

// ---------------- K2: GATv2 attention, one warp per (b, dst) ---------------
// online softmax; xl[s] row stays in registers for both score and aggregate.
__global__ void __launch_bounds__(256) k_gat(
    const float* __restrict__ att, const float* __restrict__ gat_bias,
    const float* __restrict__ bias_gc, int B)
{
    int gw = (blockIdx.x * blockDim.x + threadIdx.x) >> 5;
    int lane = threadIdx.x & 31;
    if (gw >= B * NN) return;
    int b = gw / NN, d = gw % NN;

    const float* xrp = g_xr + (size_t)gw * UU;
    float xrv[4], attv[4], bias[4];
    #pragma unroll
    for (int j = 0; j < 4; ++j) {
        int u = lane + 32 * j;
        if (u < UU) { xrv[j] = xrp[u]; attv[j] = att[u]; bias[j] = gat_bias[u] + bias_gc[u]; }
        else        { xrv[j] = 0.f;    attv[j] = 0.f;    bias[j] = 0.f; }
    }
    float m = -1e30f, Z = 0.f, acc[4] = {0.f, 0.f, 0.f, 0.f};
    int beg = g_rowptr[d], end = g_rowptr[d + 1];
    for (int k = beg; k < end; ++k) {
        int s = g_col[k];
        const float* xls = g_xl + ((size_t)b * NN + s) * UU;
        float mv[4];
        float part = 0.f;
        #pragma unroll
        for (int j = 0; j < 4; ++j) {
            int u = lane + 32 * j;
            mv[j] = 0.f;
            if (u < UU) {
                mv[j] = xls[u];
                float t = mv[j] + xrv[j];
                t = t > 0.f ? t : 0.2f * t;
                part += attv[j] * t;
            }
        }
        #pragma unroll
        for (int off = 16; off; off >>= 1) part += __shfl_xor_sync(0xffffffffu, part, off);
        float e  = part;
        float nm = fmaxf(m, e);
        float c1 = __expf(m - nm);
        float c2 = __expf(e - nm);
        Z = Z * c1 + c2;
        #pragma unroll
        for (int j = 0; j < 4; ++j) acc[j] = acc[j] * c1 + c2 * mv[j];
        m = nm;
    }
    float inv = 1.f / Z;
    float* stp = g_st + (size_t)gw * UU;
    #pragma unroll
    for (int j = 0; j < 4; ++j) {
        int u = lane + 32 * j;
        if (u < UU) stp[u] = acc[j] * inv + bias[j];
    }
}

// ---------------- K3: fused GRU ---------------------------------------------
// x = [inputs(3) | st(100)] ; gates = sigmoid(x@W1+b1); c = tanh([inputs|r*st]@W2+b2)
// out = u*st + (1-u)*c. Both weight matrices resident in smem; 4 rows/warp.
__global__ void __launch_bounds__(256) k_gru(
    const float* __restrict__ inputs,
    const float* __restrict__ W1, const float* __restrict__ b1,
    const float* __restrict__ W2, const float* __restrict__ b2,
    float* __restrict__ out, int BROWS)
{
    extern __shared__ float sm[];
    float* sW1 = sm;                     // 103*200
    float* sW2 = sm + FI * 2 * UU;       // 103*100
    float* dyn = sW2 + FI * UU;
    int warp = threadIdx.x >> 5, lane = threadIdx.x & 31, nw = blockDim.x >> 5;
    float* wb  = dyn + warp * 1616;
    float* SX  = wb;            // [4][104]
    float* SST = wb + 416;      // [4][100]
    float* SR  = SST + 400;     // [4][100]
    float* SU  = SR + 400;      // [4][100]

    for (int i = threadIdx.x; i < FI * 2 * UU; i += blockDim.x) sW1[i] = W1[i];
    for (int i = threadIdx.x; i < FI * UU;     i += blockDim.x) sW2[i] = W2[i];
    __syncthreads();

    float b1r[4] = {}, b1u[4] = {}, b2v[4] = {};
    if (lane < 25) {
        #pragma unroll
        for (int j = 0; j < 4; ++j) {
            b1r[j] = b1[4 * lane + j];
            b1u[j] = b1[UU + 4 * lane + j];
            b2v[j] = b2[4 * lane + j];
        }
    }

    int ngroups = (BROWS + 3) >> 2;
    for (int g = blockIdx.x * nw + warp; g < ngroups; g += gridDim.x * nw) {
        int row0 = g * 4;
        for (int r = 0; r < 4; ++r) {
            int row = min(row0 + r, BROWS - 1);
            const float* sp = g_st + (size_t)row * UU;
            for (int i = lane; i < UU; i += 32) {
                float v = sp[i];
                SX[r * 104 + 3 + i] = v;
                SST[r * 100 + i] = v;
            }
            if (lane < 3) {
                int b = row / NN, n = row % NN;
                SX[r * 104 + lane] = inputs[(size_t)b * (NN * 3) + n * 3 + lane];
            }
        }
        __syncwarp();

        // ---- GEMM1: 200 outputs (r cols 4t..4t+3, u cols 100+4t..4t+3) ----
        if (lane < 25) {
            float ar[4][4], au[4][4];
            #pragma unroll
            for (int r = 0; r < 4; ++r)
                #pragma unroll
                for (int j = 0; j < 4; ++j) { ar[r][j] = b1r[j]; au[r][j] = b1u[j]; }
            #pragma unroll 1
            for (int q = 0; q < 25; ++q) {
                float xs[4][4];
                #pragma unroll
                for (int r = 0; r < 4; ++r) {
                    float4 t = *(const float4*)&SX[r * 104 + 4 * q];
                    xs[r][0] = t.x; xs[r][1] = t.y; xs[r][2] = t.z; xs[r][3] = t.w;
                }
                #pragma unroll
                for (int ff = 0; ff < 4; ++ff) {
                    int f = 4 * q + ff;
                    float4 wr = *(const float4*)&sW1[f * 200 + 4 * lane];
                    float4 wu = *(const float4*)&sW1[f * 200 + UU + 4 * lane];
                    #pragma unroll
                    for (int r = 0; r < 4; ++r) {
                        float x = xs[r][ff];
                        ar[r][0] = fmaf(x, wr.x, ar[r][0]);
                        ar[r][1] = fmaf(x, wr.y, ar[r][1]);
                        ar[r][2] = fmaf(x, wr.z, ar[r][2]);
                        ar[r][3] = fmaf(x, wr.w, ar[r][3]);
                        au[r][0] = fmaf(x, wu.x, au[r][0]);
                        au[r][1] = fmaf(x, wu.y, au[r][1]);
                        au[r][2] = fmaf(x, wu.z, au[r][2]);
                        au[r][3] = fmaf(x, wu.w, au[r][3]);
                    }
                }
            }
            #pragma unroll
            for (int f = 100; f < 103; ++f) {
                float4 wr = *(const float4*)&sW1[f * 200 + 4 * lane];
                float4 wu = *(const float4*)&sW1[f * 200 + UU + 4 * lane];
                #pragma unroll
                for (int r = 0; r < 4; ++r) {
                    float x = SX[r * 104 + f];
                    ar[r][0] = fmaf(x, wr.x, ar[r][0]);
                    ar[r][1] = fmaf(x, wr.y, ar[r][1]);
                    ar[r][2] = fmaf(x, wr.z, ar[r][2]);
                    ar[r][3] = fmaf(x, wr.w, ar[r][3]);
                    au[r][0] = fmaf(x, wu.x, au[r][0]);
                    au[r][1] = fmaf(x, wu.y, au[r][1]);
                    au[r][2] = fmaf(x, wu.z, au[r][2]);
                    au[r][3] = fmaf(x, wu.w, au[r][3]);
                }
            }
            #pragma unroll
            for (int r = 0; r < 4; ++r)
                #pragma unroll
                for (int j = 0; j < 4; ++j) {
                    SR[r * 100 + 4 * lane + j] = 1.f / (1.f + __expf(-ar[r][j]));
                    SU[r * 100 + 4 * lane + j] = 1.f / (1.f + __expf(-au[r][j]));
                }
        }
        __syncwarp();

        // ---- x2: hidden part becomes r*st ----
        for (int r = 0; r < 4; ++r)
            for (int i = lane; i < UU; i += 32)
                SX[r * 104 + 3 + i] = SR[r * 100 + i] * SST[r * 100 + i];
        __syncwarp();

        // ---- GEMM2 + gate + output ----
        if (lane < 25) {
            float a2[4][4];
            #pragma unroll
            for (int r = 0; r < 4; ++r)
                #pragma unroll
                for (int j = 0; j < 4; ++j) a2[r][j] = b2v[j];
            #pragma unroll 1
            for (int q = 0; q < 25; ++q) {
                float xs[4][4];
                #pragma unroll
                for (int r = 0; r < 4; ++r) {
                    float4 t = *(const float4*)&SX[r * 104 + 4 * q];
                    xs[r][0] = t.x; xs[r][1] = t.y; xs[r][2] = t.z; xs[r][3] = t.w;
                }
                #pragma unroll
                for (int ff = 0; ff < 4; ++ff) {
                    int f = 4 * q + ff;
                    float4 w = *(const float4*)&sW2[f * UU + 4 * lane];
                    #pragma unroll
                    for (int r = 0; r < 4; ++r) {
                        float x = xs[r][ff];
                        a2[r][0] = fmaf(x, w.x, a2[r][0]);
                        a2[r][1] = fmaf(x, w.y, a2[r][1]);
                        a2[r][2] = fmaf(x, w.z, a2[r][2]);
                        a2[r][3] = fmaf(x, w.w, a2[r][3]);
                    }
                }
            }
            #pragma unroll
            for (int f = 100; f < 103; ++f) {
                float4 w = *(const float4*)&sW2[f * UU + 4 * lane];
                #pragma unroll
                for (int r = 0; r < 4; ++r) {
                    float x = SX[r * 104 + f];
                    a2[r][0] = fmaf(x, w.x, a2[r][0]);
                    a2[r][1] = fmaf(x, w.y, a2[r][1]);
                    a2[r][2] = fmaf(x, w.z, a2[r][2]);
                    a2[r][3] = fmaf(x, w.w, a2[r][3]);
                }
            }
            #pragma unroll
            for (int r = 0; r < 4; ++r) {
                size_t row = min(row0 + r, BROWS - 1);
                float4 uv  = *(const float4*)&SU[r * 100 + 4 * lane];
                float4 stv = *(const float4*)&SST[r * 100 + 4 * lane];
                float4 o;
                o.x = uv.x * stv.x + (1.f - uv.x) * tanhf(a2[r][0]);
                o.y = uv.y * stv.y + (1.f - uv.y) * tanhf(a2[r][1]);
                o.z = uv.z * stv.z + (1.f - uv.z) * tanhf(a2[r][2]);
                o.w = uv.w * stv.w + (1.f - uv.w) * tanhf(a2[r][3]);
                *(float4*)&out[row * UU + 4 * lane] = o;
            }
        }
        __syncwarp();
    }
}

// ---------------- launch ----------------------------------------------------
extern "C" void kernel_launch(void* const* d_in, const int* in_sizes, int n_in,
                              void* d_out, int out_size)
{
    const float* inputs   = (const float*)d_in[0];
    const float* state    = (const float*)d_in[1];
    const int*   src      = (const int*)d_in[2];
    const int*   dst      = (const int*)d_in[3];
    const float* Wl       = (const float*)d_in[4];
    const float* Wr       = (const float*)d_in[5];
    const float* att      = (const float*)d_in[6];
    const float* gat_bias = (const float*)d_in[7];
    const float* bias_gc  = (const float*)d_in[8];
    const float* W1       = (const float*)d_in[9];
    const float* b1       = (const float*)d_in[10];
    const float* W2       = (const float*)d_in[11];
    const float* b2       = (const float*)d_in[12];
    float* out = (float*)d_out;

    int B = in_sizes[1] / (NN * UU);
    if (B > MAXB) B = MAXB;
    int E = in_sizes[2];
    int BROWS = B * NN;

    const int SMEM1 = (2 * FI * UU + 8 * 4 * 104) * 4;          // 95,712 B
    const int SMEM3 = (3 * FI * UU + 8 * 1616) * 4;             // 175,312 B
    cudaFuncSetAttribute(k_xfrm, cudaFuncAttributeMaxDynamicSharedMemorySize, SMEM1);
    cudaFuncSetAttribute(k_gru,  cudaFuncAttributeMaxDynamicSharedMemorySize, SMEM3);

    k_csr_count<<<1, 256>>>(dst, E);
    k_csr_fill<<<NN, 32>>>(src, dst, E);
    k_xfrm<<<296, 256, SMEM1>>>(state, inputs, Wl, Wr, BROWS);
    int gat_blocks = (BROWS * 32 + 255) / 256;
    k_gat<<<gat_blocks, 256>>>(att, gat_bias, bias_gc, B);
    k_gru<<<148, 256, SMEM3>>>(inputs, W1, b1, W2, b2, out, BROWS);
}